// round 1
// baseline (speedup 1.0000x reference)
#include <cuda_runtime.h>
#include <math.h>

// Problem constants
#define NROWS 65536
#define DDIM  1024
#define HDIM  512
#define HHALF 256
#define RREG  16
#define MPATCH 4096          // NROWS / RREG
#define NCHUNK 32            // pool chunks per region
#define MCHUNK (MPATCH / NCHUNK)  // 128 rows per chunk

// ---------------- scratch (device globals: sanctioned, no allocations) ---------
__device__ float g_H[(size_t)NROWS * HDIM];     // 128 MB  region_emb (post-GELU)
__device__ float g_T[(size_t)NROWS * HHALF];    // 64 MB   tanh(H@Wa1+ba1)
__device__ float g_scores[NROWS];
__device__ float g_w[NROWS];                    // normalized softmax weights
__device__ float g_PF[RREG * NCHUNK * HDIM];    // 1 MB    partial pooled features

__device__ __forceinline__ float gelu_exact(float x) {
    return 0.5f * x * (1.0f + erff(x * 0.7071067811865476f));
}

// ---------------- generic tiled GEMM: C = act(A[MxK] @ B[KxN] + bias) ----------
// BM=128, BN=64, BK=16, 256 threads, 8x4 microtile. Dims must divide tiles.
// ACT: 0 none, 1 gelu(erf), 2 tanh
template <int ACT>
__global__ __launch_bounds__(256)
void gemm_bias_act(const float* __restrict__ A, const float* __restrict__ B,
                   const float* __restrict__ bias, float* __restrict__ C,
                   int K, int N)
{
    constexpr int BM = 128, BN = 64, BK = 16, TM = 8, TN = 4;
    __shared__ float As[BK * BM];   // transposed: As[k][m]
    __shared__ float Bs[BK * BN];   // Bs[k][n]

    const int tid = threadIdx.x;
    const int tx  = tid & 15;   // n direction (16 x TN=4 -> 64)
    const int ty  = tid >> 4;   // m direction (16 x TM=8 -> 128)
    const int bm  = blockIdx.y;
    const int bn  = blockIdx.x;

    const float* Ag = A + (size_t)bm * BM * K;
    const float* Bg = B + (size_t)bn * BN;

    float acc[TM][TN];
#pragma unroll
    for (int i = 0; i < TM; i++)
#pragma unroll
        for (int j = 0; j < TN; j++) acc[i][j] = 0.0f;

    for (int k0 = 0; k0 < K; k0 += BK) {
        // A tile: 128x16 = 512 float4, 2 per thread; store transposed
#pragma unroll
        for (int l = 0; l < 2; l++) {
            int f   = tid + l * 256;      // 0..511
            int row = f >> 2;             // 0..127
            int cv  = f & 3;              // float4 within 16 cols
            float4 v = *reinterpret_cast<const float4*>(Ag + (size_t)row * K + k0 + cv * 4);
            As[(cv * 4 + 0) * BM + row] = v.x;
            As[(cv * 4 + 1) * BM + row] = v.y;
            As[(cv * 4 + 2) * BM + row] = v.z;
            As[(cv * 4 + 3) * BM + row] = v.w;
        }
        // B tile: 16x64 = 256 float4, 1 per thread
        {
            int row = tid >> 4;           // 0..15
            int cv  = tid & 15;           // 0..15
            float4 v = *reinterpret_cast<const float4*>(Bg + (size_t)(k0 + row) * N + cv * 4);
            *reinterpret_cast<float4*>(&Bs[row * BN + cv * 4]) = v;
        }
        __syncthreads();

#pragma unroll
        for (int kk = 0; kk < BK; kk++) {
            float a[TM], b[TN];
            float4 a0 = *reinterpret_cast<const float4*>(&As[kk * BM + ty * TM]);
            float4 a1 = *reinterpret_cast<const float4*>(&As[kk * BM + ty * TM + 4]);
            a[0] = a0.x; a[1] = a0.y; a[2] = a0.z; a[3] = a0.w;
            a[4] = a1.x; a[5] = a1.y; a[6] = a1.z; a[7] = a1.w;
            float4 b0 = *reinterpret_cast<const float4*>(&Bs[kk * BN + tx * TN]);
            b[0] = b0.x; b[1] = b0.y; b[2] = b0.z; b[3] = b0.w;
#pragma unroll
            for (int i = 0; i < TM; i++)
#pragma unroll
                for (int j = 0; j < TN; j++)
                    acc[i][j] = fmaf(a[i], b[j], acc[i][j]);
        }
        __syncthreads();
    }

    const int col0 = bn * BN + tx * TN;
    float bi[TN];
#pragma unroll
    for (int j = 0; j < TN; j++) bi[j] = bias[col0 + j];
#pragma unroll
    for (int i = 0; i < TM; i++) {
        int row = bm * BM + ty * TM + i;
        float4 o;
        float v0 = acc[i][0] + bi[0];
        float v1 = acc[i][1] + bi[1];
        float v2 = acc[i][2] + bi[2];
        float v3 = acc[i][3] + bi[3];
        if (ACT == 1) { v0 = gelu_exact(v0); v1 = gelu_exact(v1); v2 = gelu_exact(v2); v3 = gelu_exact(v3); }
        if (ACT == 2) { v0 = tanhf(v0); v1 = tanhf(v1); v2 = tanhf(v2); v3 = tanhf(v3); }
        o.x = v0; o.y = v1; o.z = v2; o.w = v3;
        *reinterpret_cast<float4*>(C + (size_t)row * N + col0) = o;
    }
}

// ---------------- scores[i] = T[i,:] . Wa2 + ba2  (one warp per row) ----------
__global__ __launch_bounds__(256)
void score_kernel(const float* __restrict__ Wa2, const float* __restrict__ ba2)
{
    int warp = threadIdx.x >> 5;
    int lane = threadIdx.x & 31;
    int row  = blockIdx.x * 8 + warp;
    const float* t = g_T + (size_t)row * HHALF;
    float s = 0.0f;
#pragma unroll
    for (int i = 0; i < 8; i++) {
        int k = lane + i * 32;
        s = fmaf(t[k], Wa2[k], s);
    }
#pragma unroll
    for (int o = 16; o > 0; o >>= 1) s += __shfl_down_sync(0xffffffffu, s, o);
    if (lane == 0) g_scores[row] = s + ba2[0];
}

// ---------------- per-region softmax over the 4096 strided scores -------------
__global__ __launch_bounds__(256)
void softmax_region()
{
    int r = blockIdx.x;          // 16 regions
    int tid = threadIdx.x;       // 256
    __shared__ float red[256];

    float mx = -1e30f;
    for (int m = tid; m < MPATCH; m += 256) mx = fmaxf(mx, g_scores[m * RREG + r]);
    red[tid] = mx; __syncthreads();
    for (int o = 128; o > 0; o >>= 1) { if (tid < o) red[tid] = fmaxf(red[tid], red[tid + o]); __syncthreads(); }
    mx = red[0]; __syncthreads();

    float sm = 0.0f;
    for (int m = tid; m < MPATCH; m += 256) sm += expf(g_scores[m * RREG + r] - mx);
    red[tid] = sm; __syncthreads();
    for (int o = 128; o > 0; o >>= 1) { if (tid < o) red[tid] += red[tid + o]; __syncthreads(); }
    float inv = 1.0f / red[0];

    for (int m = tid; m < MPATCH; m += 256)
        g_w[m * RREG + r] = expf(g_scores[m * RREG + r] - mx) * inv;
}

// ---------------- weighted pooling: partial region features ------------------
__global__ __launch_bounds__(512)
void pool_partial()
{
    int r  = blockIdx.x;    // 16 regions
    int ch = blockIdx.y;    // 32 chunks
    int c  = threadIdx.x;   // 512 = HDIM
    float acc = 0.0f;
    int m0 = ch * MCHUNK;
#pragma unroll 4
    for (int mm = 0; mm < MCHUNK; mm++) {
        int row = (m0 + mm) * RREG + r;
        acc = fmaf(g_H[(size_t)row * HDIM + c], g_w[row], acc);
    }
    g_PF[(r * NCHUNK + ch) * HDIM + c] = acc;
}

// ---------------- single-block slide encoder + attention + classifier --------
__global__ __launch_bounds__(512)
void slide_kernel(const float* __restrict__ Ws,  const float* __restrict__ bs,
                  const float* __restrict__ Wsa1, const float* __restrict__ bsa1,
                  const float* __restrict__ Wsa2, const float* __restrict__ bsa2,
                  const float* __restrict__ Wc1, const float* __restrict__ bc1,
                  const float* __restrict__ Wc2, const float* __restrict__ bc2,
                  float* __restrict__ out)
{
    extern __shared__ float smf[];
    float* sRF   = smf;                 // 16*512
    float* sSE   = smf + 8192;          // 16*512
    float* sRep  = smf + 16384;         // 512
    float* sAtt  = smf + 16896;         // 16
    float* sWred = smf + 16912;         // 256

    int tid  = threadIdx.x;  // 512
    int lane = tid & 31, wp = tid >> 5;

    // 1. region_features = sum over 32 partials
    for (int idx = tid; idx < RREG * HDIM; idx += 512) {
        int r = idx >> 9, c = idx & 511;
        float s = 0.0f;
#pragma unroll
        for (int j = 0; j < NCHUNK; j++) s += g_PF[(r * NCHUNK + j) * HDIM + c];
        sRF[idx] = s;
    }
    __syncthreads();

    // 2. slide_emb[r][g] = gelu(RF[r,:] @ Ws[:,g] + bs[g]); g = tid
    {
        float accv[RREG];
        float bg = bs[tid];
#pragma unroll
        for (int r = 0; r < RREG; r++) accv[r] = bg;
        for (int h = 0; h < HDIM; h++) {
            float wg = Ws[h * HDIM + tid];
#pragma unroll
            for (int r = 0; r < RREG; r++) accv[r] = fmaf(sRF[r * HDIM + h], wg, accv[r]);
        }
#pragma unroll
        for (int r = 0; r < RREG; r++) sSE[r * HDIM + tid] = gelu_exact(accv[r]);
    }
    __syncthreads();

    // 3. slide attention logits: sattn[r] = sum_k tanh(SE[r,:]@Wsa1[:,k]+bsa1[k]) * Wsa2[k] + bsa2
    {
        float contrib[RREG];
        if (tid < HHALF) {
            float acc[RREG];
            float bk = bsa1[tid];
#pragma unroll
            for (int r = 0; r < RREG; r++) acc[r] = bk;
            for (int h = 0; h < HDIM; h++) {
                float wv = Wsa1[h * HHALF + tid];
#pragma unroll
                for (int r = 0; r < RREG; r++) acc[r] = fmaf(sSE[r * HDIM + h], wv, acc[r]);
            }
            float w2 = Wsa2[tid];
#pragma unroll
            for (int r = 0; r < RREG; r++) contrib[r] = tanhf(acc[r]) * w2;
        } else {
#pragma unroll
            for (int r = 0; r < RREG; r++) contrib[r] = 0.0f;
        }
#pragma unroll
        for (int r = 0; r < RREG; r++) {
            float v = contrib[r];
#pragma unroll
            for (int o = 16; o > 0; o >>= 1) v += __shfl_down_sync(0xffffffffu, v, o);
            if (lane == 0) sWred[wp * RREG + r] = v;
        }
        __syncthreads();
        if (tid < RREG) {
            float s = 0.0f;
#pragma unroll
            for (int j = 0; j < 16; j++) s += sWred[j * RREG + tid];
            sAtt[tid] = s + bsa2[0];
        }
        __syncthreads();
        if (tid == 0) {   // softmax over 16 regions
            float mx = -1e30f;
            for (int r = 0; r < RREG; r++) mx = fmaxf(mx, sAtt[r]);
            float sum = 0.0f;
            for (int r = 0; r < RREG; r++) { float e = expf(sAtt[r] - mx); sAtt[r] = e; sum += e; }
            float inv = 1.0f / sum;
            for (int r = 0; r < RREG; r++) sAtt[r] *= inv;
        }
        __syncthreads();
    }

    // 4. slide_rep[h] = sum_r SE[r][h] * w[r]
    {
        float rep = 0.0f;
#pragma unroll
        for (int r = 0; r < RREG; r++) rep = fmaf(sSE[r * HDIM + tid], sAtt[r], rep);
        sRep[tid] = rep;
    }
    __syncthreads();

    // 5. classifier
    {
        float c0 = 0.0f, c1 = 0.0f;
        if (tid < HHALF) {
            float a = bc1[tid];
            for (int h = 0; h < HDIM; h++) a = fmaf(sRep[h], Wc1[h * HHALF + tid], a);
            float g = gelu_exact(a);
            c0 = g * Wc2[tid * 2 + 0];
            c1 = g * Wc2[tid * 2 + 1];
        }
#pragma unroll
        for (int o = 16; o > 0; o >>= 1) {
            c0 += __shfl_down_sync(0xffffffffu, c0, o);
            c1 += __shfl_down_sync(0xffffffffu, c1, o);
        }
        if (lane == 0) { sWred[wp * 2] = c0; sWred[wp * 2 + 1] = c1; }
        __syncthreads();
        if (tid == 0) {
            float l0 = 0.0f, l1 = 0.0f;
#pragma unroll
            for (int j = 0; j < 16; j++) { l0 += sWred[j * 2]; l1 += sWred[j * 2 + 1]; }
            out[0] = l0 + bc2[0];
            out[1] = l1 + bc2[1];
        }
    }
}

// -------------------------------- launch --------------------------------------
extern "C" void kernel_launch(void* const* d_in, const int* in_sizes, int n_in,
                              void* d_out, int out_size)
{
    const float* emb  = (const float*)d_in[0];
    const float* W1   = (const float*)d_in[1];
    const float* b1   = (const float*)d_in[2];
    const float* Wa1  = (const float*)d_in[3];
    const float* ba1  = (const float*)d_in[4];
    const float* Wa2  = (const float*)d_in[5];
    const float* ba2  = (const float*)d_in[6];
    const float* Ws   = (const float*)d_in[7];
    const float* bs   = (const float*)d_in[8];
    const float* Wsa1 = (const float*)d_in[9];
    const float* bsa1 = (const float*)d_in[10];
    const float* Wsa2 = (const float*)d_in[11];
    const float* bsa2 = (const float*)d_in[12];
    const float* Wc1  = (const float*)d_in[13];
    const float* bc1  = (const float*)d_in[14];
    const float* Wc2  = (const float*)d_in[15];
    const float* bc2  = (const float*)d_in[16];
    float* out = (float*)d_out;

    float *gH, *gT;
    cudaGetSymbolAddress((void**)&gH, g_H);
    cudaGetSymbolAddress((void**)&gT, g_T);

    // 1. region encoder: H = gelu(E @ W1 + b1)   (65536x1024x512)
    gemm_bias_act<1><<<dim3(HDIM / 64, NROWS / 128), 256>>>(emb, W1, b1, gH, DDIM, HDIM);
    // 2. attention hidden: T = tanh(H @ Wa1 + ba1)  (65536x512x256)
    gemm_bias_act<2><<<dim3(HHALF / 64, NROWS / 128), 256>>>(gH, Wa1, ba1, gT, HDIM, HHALF);
    // 3. scores = T . Wa2 + ba2
    score_kernel<<<NROWS / 8, 256>>>(Wa2, ba2);
    // 4. per-region softmax -> normalized weights
    softmax_region<<<RREG, 256>>>();
    // 5. weighted pool partials
    pool_partial<<<dim3(RREG, NCHUNK), 512>>>();
    // 6. slide encoder + attention + classifier
    const int SLIDE_SMEM = (2 * RREG * HDIM + HDIM + RREG + 256) * (int)sizeof(float);
    cudaFuncSetAttribute(slide_kernel, cudaFuncAttributeMaxDynamicSharedMemorySize, SLIDE_SMEM);
    slide_kernel<<<1, 512, SLIDE_SMEM>>>(Ws, bs, Wsa1, bsa1, Wsa2, bsa2,
                                         Wc1, bc1, Wc2, bc2, out);
}

// round 14
// speedup vs baseline: 4.0654x; 4.0654x over previous
#include <cuda_runtime.h>
#include <cuda_bf16.h>
#include <math.h>
#include <stdint.h>

// Problem constants
#define NROWS 65536
#define DDIM  1024
#define HDIM  512
#define HHALF 256
#define RREG  16
#define MPATCH 4096
#define NCHUNK 32
#define MCHUNK (MPATCH / NCHUNK)

// ---------------- scratch (device globals) ------------------------------------
__device__ __nv_bfloat16 g_Ebf[(size_t)NROWS * DDIM];    // 128 MB  bf16 embeddings
__device__ __nv_bfloat16 g_W1bf[(size_t)HDIM * DDIM];    // 1 MB    W1^T  [n][k]
__device__ __nv_bfloat16 g_Wa1bf[(size_t)HHALF * HDIM];  // 0.25 MB Wa1^T [n][k]
__device__ __nv_bfloat16 g_Hbf[(size_t)NROWS * HDIM];    // 64 MB   region_emb bf16
__device__ float         g_T[(size_t)NROWS * HHALF];     // 64 MB   tanh hidden
__device__ float g_scores[NROWS];
__device__ float g_w[NROWS];
__device__ float g_PF[RREG * NCHUNK * HDIM];

__device__ __forceinline__ float gelu_exact(float x) {
    return 0.5f * x * (1.0f + erff(x * 0.7071067811865476f));
}

__device__ __forceinline__ uint32_t smem_u32(const void* p) {
    uint32_t a;
    asm("{ .reg .u64 t; cvta.to.shared.u64 t, %1; cvt.u32.u64 %0, t; }" : "=r"(a) : "l"(p));
    return a;
}

// ---------------- baseline-ISA tensor-core primitives --------------------------
__device__ __forceinline__ void ldmatrix_x4(uint32_t* r, uint32_t addr) {
    asm volatile("ldmatrix.sync.aligned.m8n8.x4.shared.b16 {%0,%1,%2,%3}, [%4];"
                 : "=r"(r[0]), "=r"(r[1]), "=r"(r[2]), "=r"(r[3]) : "r"(addr));
}
__device__ __forceinline__ void mma_bf16(float* d, const uint32_t* a, const uint32_t* b) {
    asm volatile(
        "mma.sync.aligned.m16n8k16.row.col.f32.bf16.bf16.f32 "
        "{%0,%1,%2,%3}, {%4,%5,%6,%7}, {%8,%9}, {%0,%1,%2,%3};"
        : "+f"(d[0]), "+f"(d[1]), "+f"(d[2]), "+f"(d[3])
        : "r"(a[0]), "r"(a[1]), "r"(a[2]), "r"(a[3]), "r"(b[0]), "r"(b[1]));
}
__device__ __forceinline__ void cp_async16(uint32_t smem_addr, const void* gptr) {
    asm volatile("cp.async.cg.shared.global [%0], [%1], 16;"
                 :: "r"(smem_addr), "l"(gptr) : "memory");
}
#define CP_ASYNC_COMMIT() asm volatile("cp.async.commit_group;" ::: "memory")
#define CP_ASYNC_WAIT(n)  asm volatile("cp.async.wait_group %0;" :: "n"(n) : "memory")

// ---------------- conversion kernels ------------------------------------------
__global__ __launch_bounds__(256) void conv_bf16(const float* __restrict__ in,
                                                 __nv_bfloat16* __restrict__ out) {
    size_t i = ((size_t)blockIdx.x * 256 + threadIdx.x) * 8;
    float4 a = *reinterpret_cast<const float4*>(in + i);
    float4 b = *reinterpret_cast<const float4*>(in + i + 4);
    __nv_bfloat162 p0 = __float22bfloat162_rn(make_float2(a.x, a.y));
    __nv_bfloat162 p1 = __float22bfloat162_rn(make_float2(a.z, a.w));
    __nv_bfloat162 p2 = __float22bfloat162_rn(make_float2(b.x, b.y));
    __nv_bfloat162 p3 = __float22bfloat162_rn(make_float2(b.z, b.w));
    uint4 o;
    o.x = *reinterpret_cast<uint32_t*>(&p0);
    o.y = *reinterpret_cast<uint32_t*>(&p1);
    o.z = *reinterpret_cast<uint32_t*>(&p2);
    o.w = *reinterpret_cast<uint32_t*>(&p3);
    *reinterpret_cast<uint4*>(out + i) = o;
}

// out[n*K + k] = bf16(in[k*N + n])
__global__ __launch_bounds__(256) void transpose_bf16(const float* __restrict__ in,
                                                      __nv_bfloat16* __restrict__ out,
                                                      int K, int N) {
    int idx = blockIdx.x * 256 + threadIdx.x;
    int k = idx / N, n = idx % N;
    out[(size_t)n * K + k] = __float2bfloat16(in[idx]);
}

// ---------------- mma.sync GEMM: C = act(A[MxK] @ Bt[NxK]^T + bias) ------------
// CTA tile 128x128x32, 8 warps (2x4), warp tile 64x32, double-buffered cp.async.
// SMEM layout: row-major 128 rows x 32 bf16 (64B), 16B chunks swizzled by
// chunk ^= (row>>1)&3  (conflict-free ldmatrix phases).
template <int ACT, bool WRITE_F32, bool WRITE_BF16>
__global__ __launch_bounds__(256)
void gemm_mma(const __nv_bfloat16* __restrict__ A, const __nv_bfloat16* __restrict__ Bt,
              const float* __restrict__ bias, float* __restrict__ C,
              __nv_bfloat16* __restrict__ Cbf, int K, int N)
{
    __shared__ __nv_bfloat16 sA[2][128 * 32];
    __shared__ __nv_bfloat16 sB[2][128 * 32];

    const int tid  = threadIdx.x;
    const int lane = tid & 31;
    const int wid  = tid >> 5;
    const int wm   = wid >> 2;          // 0..1  -> rows wm*64
    const int wn   = wid & 3;           // 0..3  -> cols wn*32
    const int m0   = blockIdx.y * 128;
    const int n0   = blockIdx.x * 128;

    float acc[4][4][4];
#pragma unroll
    for (int i = 0; i < 4; i++)
#pragma unroll
        for (int j = 0; j < 4; j++)
#pragma unroll
            for (int v = 0; v < 4; v++) acc[i][j][v] = 0.0f;

    const uint32_t sA0 = smem_u32(sA[0]), sA1 = smem_u32(sA[1]);
    const uint32_t sB0 = smem_u32(sB[0]), sB1 = smem_u32(sB[1]);

    // per-thread load coords: 512 chunks of 16B per tile, 2 per thread
    const int f0row = (tid + 0)   >> 2, f0ch = (tid + 0)   & 3;
    const int f1row = (tid + 256) >> 2, f1ch = (tid + 256) & 3;
    const uint32_t d0 = f0row * 64 + ((f0ch ^ ((f0row >> 1) & 3)) << 4);
    const uint32_t d1 = f1row * 64 + ((f1ch ^ ((f1row >> 1) & 3)) << 4);

    auto load_tile = [&](int stage, int k0) {
        uint32_t a_s = stage ? sA1 : sA0;
        uint32_t b_s = stage ? sB1 : sB0;
        cp_async16(a_s + d0, A  + (size_t)(m0 + f0row) * K + k0 + f0ch * 8);
        cp_async16(a_s + d1, A  + (size_t)(m0 + f1row) * K + k0 + f1ch * 8);
        cp_async16(b_s + d0, Bt + (size_t)(n0 + f0row) * K + k0 + f0ch * 8);
        cp_async16(b_s + d1, Bt + (size_t)(n0 + f1row) * K + k0 + f1ch * 8);
        CP_ASYNC_COMMIT();
    };

    const int ntiles = K >> 5;          // K/32
    load_tile(0, 0);

    for (int t = 0; t < ntiles; t++) {
        if (t + 1 < ntiles) {
            load_tile((t + 1) & 1, (t + 1) << 5);
            CP_ASYNC_WAIT(1);
        } else {
            CP_ASYNC_WAIT(0);
        }
        __syncthreads();

        const int s = t & 1;
        const uint32_t aBase = s ? sA1 : sA0;
        const uint32_t bBase = s ? sB1 : sB0;

#pragma unroll
        for (int ks = 0; ks < 2; ks++) {
            uint32_t aF[4][4];
#pragma unroll
            for (int mi = 0; mi < 4; mi++) {
                int row = wm * 64 + mi * 16 + (lane & 15);
                int ci  = ks * 2 + (lane >> 4);
                uint32_t addr = aBase + row * 64 + (((ci ^ ((row >> 1) & 3))) << 4);
                ldmatrix_x4(aF[mi], addr);
            }
            uint32_t bF[4][2];
#pragma unroll
            for (int p = 0; p < 2; p++) {
                int row = wn * 32 + p * 16 + ((lane & 7) | ((lane & 16) >> 1));
                int ci  = ks * 2 + ((lane >> 3) & 1);
                uint32_t addr = bBase + row * 64 + (((ci ^ ((row >> 1) & 3))) << 4);
                uint32_t r[4];
                ldmatrix_x4(r, addr);
                bF[2 * p + 0][0] = r[0]; bF[2 * p + 0][1] = r[1];
                bF[2 * p + 1][0] = r[2]; bF[2 * p + 1][1] = r[3];
            }
#pragma unroll
            for (int mi = 0; mi < 4; mi++)
#pragma unroll
                for (int j = 0; j < 4; j++)
                    mma_bf16(acc[mi][j], aF[mi], bF[j]);
        }
        __syncthreads();
    }

    // epilogue: bias + activation + store
    const int g  = lane >> 2;           // row group 0..7
    const int cc = (lane & 3) * 2;      // col pair
#pragma unroll
    for (int mi = 0; mi < 4; mi++) {
#pragma unroll
        for (int j = 0; j < 4; j++) {
            int col = n0 + wn * 32 + j * 8 + cc;
            float b0 = bias[col], b1 = bias[col + 1];
#pragma unroll
            for (int h = 0; h < 2; h++) {   // h=0: row g, h=1: row g+8
                int row = m0 + wm * 64 + mi * 16 + g + h * 8;
                float v0 = acc[mi][j][2 * h + 0] + b0;
                float v1 = acc[mi][j][2 * h + 1] + b1;
                if (ACT == 1) { v0 = gelu_exact(v0); v1 = gelu_exact(v1); }
                if (ACT == 2) { v0 = tanhf(v0); v1 = tanhf(v1); }
                if (WRITE_F32) {
                    float2 o; o.x = v0; o.y = v1;
                    *reinterpret_cast<float2*>(C + (size_t)row * N + col) = o;
                }
                if (WRITE_BF16) {
                    __nv_bfloat162 q = __float22bfloat162_rn(make_float2(v0, v1));
                    *reinterpret_cast<uint32_t*>(Cbf + (size_t)row * N + col) =
                        *reinterpret_cast<uint32_t*>(&q);
                }
            }
        }
    }
}

// ---------------- scores[i] = T[i,:] . Wa2 + ba2 -------------------------------
__global__ __launch_bounds__(256)
void score_kernel(const float* __restrict__ Wa2, const float* __restrict__ ba2)
{
    int warp = threadIdx.x >> 5;
    int lane = threadIdx.x & 31;
    int row  = blockIdx.x * 8 + warp;
    const float* t = g_T + (size_t)row * HHALF;
    float s = 0.0f;
#pragma unroll
    for (int i = 0; i < 8; i++) {
        int k = lane + i * 32;
        s = fmaf(t[k], Wa2[k], s);
    }
#pragma unroll
    for (int o = 16; o > 0; o >>= 1) s += __shfl_down_sync(0xffffffffu, s, o);
    if (lane == 0) g_scores[row] = s + ba2[0];
}

// ---------------- per-region softmax -------------------------------------------
__global__ __launch_bounds__(256)
void softmax_region()
{
    int r = blockIdx.x;
    int tid = threadIdx.x;
    __shared__ float red[256];

    float mx = -1e30f;
    for (int m = tid; m < MPATCH; m += 256) mx = fmaxf(mx, g_scores[m * RREG + r]);
    red[tid] = mx; __syncthreads();
    for (int o = 128; o > 0; o >>= 1) { if (tid < o) red[tid] = fmaxf(red[tid], red[tid + o]); __syncthreads(); }
    mx = red[0]; __syncthreads();

    float sm = 0.0f;
    for (int m = tid; m < MPATCH; m += 256) sm += expf(g_scores[m * RREG + r] - mx);
    red[tid] = sm; __syncthreads();
    for (int o = 128; o > 0; o >>= 1) { if (tid < o) red[tid] += red[tid + o]; __syncthreads(); }
    float inv = 1.0f / red[0];

    for (int m = tid; m < MPATCH; m += 256)
        g_w[m * RREG + r] = expf(g_scores[m * RREG + r] - mx) * inv;
}

// ---------------- weighted pooling (bf16 source, fp32 accumulate) --------------
__global__ __launch_bounds__(256)
void pool_partial()
{
    int r  = blockIdx.x;    // 16 regions
    int ch = blockIdx.y;    // 32 chunks
    int c2 = threadIdx.x;   // 256 threads, 2 cols each
    float acc0 = 0.0f, acc1 = 0.0f;
    int m0 = ch * MCHUNK;
#pragma unroll 4
    for (int mm = 0; mm < MCHUNK; mm++) {
        int row = (m0 + mm) * RREG + r;
        float w = g_w[row];
        __nv_bfloat162 hv = *reinterpret_cast<const __nv_bfloat162*>(
            g_Hbf + (size_t)row * HDIM + c2 * 2);
        float2 hf = __bfloat1622float2(hv);
        acc0 = fmaf(hf.x, w, acc0);
        acc1 = fmaf(hf.y, w, acc1);
    }
    g_PF[(r * NCHUNK + ch) * HDIM + c2 * 2 + 0] = acc0;
    g_PF[(r * NCHUNK + ch) * HDIM + c2 * 2 + 1] = acc1;
}

// ---------------- single-block slide pipeline ----------------------------------
__global__ __launch_bounds__(512)
void slide_kernel(const float* __restrict__ Ws,  const float* __restrict__ bs,
                  const float* __restrict__ Wsa1, const float* __restrict__ bsa1,
                  const float* __restrict__ Wsa2, const float* __restrict__ bsa2,
                  const float* __restrict__ Wc1, const float* __restrict__ bc1,
                  const float* __restrict__ Wc2, const float* __restrict__ bc2,
                  float* __restrict__ out)
{
    extern __shared__ float smf[];
    float* sRF   = smf;
    float* sSE   = smf + 8192;
    float* sRep  = smf + 16384;
    float* sAtt  = smf + 16896;
    float* sWred = smf + 16912;

    int tid  = threadIdx.x;
    int lane = tid & 31, wp = tid >> 5;

    for (int idx = tid; idx < RREG * HDIM; idx += 512) {
        int r = idx >> 9, c = idx & 511;
        float s = 0.0f;
#pragma unroll
        for (int j = 0; j < NCHUNK; j++) s += g_PF[(r * NCHUNK + j) * HDIM + c];
        sRF[idx] = s;
    }
    __syncthreads();

    {
        float accv[RREG];
        float bg = bs[tid];
#pragma unroll
        for (int r = 0; r < RREG; r++) accv[r] = bg;
        for (int h = 0; h < HDIM; h++) {
            float wg = Ws[h * HDIM + tid];
#pragma unroll
            for (int r = 0; r < RREG; r++) accv[r] = fmaf(sRF[r * HDIM + h], wg, accv[r]);
        }
#pragma unroll
        for (int r = 0; r < RREG; r++) sSE[r * HDIM + tid] = gelu_exact(accv[r]);
    }
    __syncthreads();

    {
        float contrib[RREG];
        if (tid < HHALF) {
            float acc[RREG];
            float bk = bsa1[tid];
#pragma unroll
            for (int r = 0; r < RREG; r++) acc[r] = bk;
            for (int h = 0; h < HDIM; h++) {
                float wv = Wsa1[h * HHALF + tid];
#pragma unroll
                for (int r = 0; r < RREG; r++) acc[r] = fmaf(sSE[r * HDIM + h], wv, acc[r]);
            }
            float w2 = Wsa2[tid];
#pragma unroll
            for (int r = 0; r < RREG; r++) contrib[r] = tanhf(acc[r]) * w2;
        } else {
#pragma unroll
            for (int r = 0; r < RREG; r++) contrib[r] = 0.0f;
        }
#pragma unroll
        for (int r = 0; r < RREG; r++) {
            float v = contrib[r];
#pragma unroll
            for (int o = 16; o > 0; o >>= 1) v += __shfl_down_sync(0xffffffffu, v, o);
            if (lane == 0) sWred[wp * RREG + r] = v;
        }
        __syncthreads();
        if (tid < RREG) {
            float s = 0.0f;
#pragma unroll
            for (int j = 0; j < 16; j++) s += sWred[j * RREG + tid];
            sAtt[tid] = s + bsa2[0];
        }
        __syncthreads();
        if (tid == 0) {
            float mx = -1e30f;
            for (int r = 0; r < RREG; r++) mx = fmaxf(mx, sAtt[r]);
            float sum = 0.0f;
            for (int r = 0; r < RREG; r++) { float e = expf(sAtt[r] - mx); sAtt[r] = e; sum += e; }
            float inv = 1.0f / sum;
            for (int r = 0; r < RREG; r++) sAtt[r] *= inv;
        }
        __syncthreads();
    }

    {
        float rep = 0.0f;
#pragma unroll
        for (int r = 0; r < RREG; r++) rep = fmaf(sSE[r * HDIM + tid], sAtt[r], rep);
        sRep[tid] = rep;
    }
    __syncthreads();

    {
        float c0 = 0.0f, c1 = 0.0f;
        if (tid < HHALF) {
            float a = bc1[tid];
            for (int h = 0; h < HDIM; h++) a = fmaf(sRep[h], Wc1[h * HHALF + tid], a);
            float g = gelu_exact(a);
            c0 = g * Wc2[tid * 2 + 0];
            c1 = g * Wc2[tid * 2 + 1];
        }
#pragma unroll
        for (int o = 16; o > 0; o >>= 1) {
            c0 += __shfl_down_sync(0xffffffffu, c0, o);
            c1 += __shfl_down_sync(0xffffffffu, c1, o);
        }
        if (lane == 0) { sWred[wp * 2] = c0; sWred[wp * 2 + 1] = c1; }
        __syncthreads();
        if (tid == 0) {
            float l0 = 0.0f, l1 = 0.0f;
#pragma unroll
            for (int j = 0; j < 16; j++) { l0 += sWred[j * 2]; l1 += sWred[j * 2 + 1]; }
            out[0] = l0 + bc2[0];
            out[1] = l1 + bc2[1];
        }
    }
}

// -------------------------------- launch ----------------------------------------
extern "C" void kernel_launch(void* const* d_in, const int* in_sizes, int n_in,
                              void* d_out, int out_size)
{
    const float* emb  = (const float*)d_in[0];
    const float* W1   = (const float*)d_in[1];
    const float* b1   = (const float*)d_in[2];
    const float* Wa1  = (const float*)d_in[3];
    const float* ba1  = (const float*)d_in[4];
    const float* Wa2  = (const float*)d_in[5];
    const float* ba2  = (const float*)d_in[6];
    const float* Ws   = (const float*)d_in[7];
    const float* bs   = (const float*)d_in[8];
    const float* Wsa1 = (const float*)d_in[9];
    const float* bsa1 = (const float*)d_in[10];
    const float* Wsa2 = (const float*)d_in[11];
    const float* bsa2 = (const float*)d_in[12];
    const float* Wc1  = (const float*)d_in[13];
    const float* bc1  = (const float*)d_in[14];
    const float* Wc2  = (const float*)d_in[15];
    const float* bc2  = (const float*)d_in[16];
    float* out = (float*)d_out;

    __nv_bfloat16 *gEbf, *gW1bf, *gWa1bf, *gHbf;
    float *gT;
    cudaGetSymbolAddress((void**)&gEbf, g_Ebf);
    cudaGetSymbolAddress((void**)&gW1bf, g_W1bf);
    cudaGetSymbolAddress((void**)&gWa1bf, g_Wa1bf);
    cudaGetSymbolAddress((void**)&gHbf, g_Hbf);
    cudaGetSymbolAddress((void**)&gT, g_T);

    // 0. bf16 conversions
    conv_bf16<<<(size_t)NROWS * DDIM / (256 * 8), 256>>>(emb, gEbf);
    transpose_bf16<<<(DDIM * HDIM) / 256, 256>>>(W1, gW1bf, DDIM, HDIM);
    transpose_bf16<<<(HDIM * HHALF) / 256, 256>>>(Wa1, gWa1bf, HDIM, HHALF);

    // 1. region encoder: Hbf = bf16(gelu(E @ W1 + b1))   (65536 x 1024 x 512)
    gemm_mma<1, false, true><<<dim3(HDIM / 128, NROWS / 128), 256>>>(
        gEbf, gW1bf, b1, (float*)nullptr, gHbf, DDIM, HDIM);
    // 2. attention hidden: T = tanh(Hbf @ Wa1 + ba1)  (65536 x 512 x 256)
    gemm_mma<2, true, false><<<dim3(HHALF / 128, NROWS / 128), 256>>>(
        gHbf, gWa1bf, ba1, gT, (__nv_bfloat16*)nullptr, HDIM, HHALF);
    // 3. scores
    score_kernel<<<NROWS / 8, 256>>>(Wa2, ba2);
    // 4. per-region softmax
    softmax_region<<<RREG, 256>>>();
    // 5. weighted pool partials (from bf16 H)
    pool_partial<<<dim3(RREG, NCHUNK), 256>>>();
    // 6. slide encoder + attention + classifier
    const int SLIDE_SMEM = (2 * RREG * HDIM + HDIM + RREG + 256) * (int)sizeof(float);
    cudaFuncSetAttribute(slide_kernel, cudaFuncAttributeMaxDynamicSharedMemorySize, SLIDE_SMEM);
    slide_kernel<<<1, 512, SLIDE_SMEM>>>(Ws, bs, Wsa1, bsa1, Wsa2, bsa2,
                                         Wc1, bc1, Wc2, bc2, out);
}

// round 16
// speedup vs baseline: 4.1736x; 1.0266x over previous
#include <cuda_runtime.h>
#include <cuda_bf16.h>
#include <math.h>
#include <stdint.h>

// Problem constants
#define NROWS 65536
#define DDIM  1024
#define HDIM  512
#define HHALF 256
#define RREG  16
#define MPATCH 4096
#define NCHUNK 32
#define MCHUNK (MPATCH / NCHUNK)

// ---------------- scratch (device globals) ------------------------------------
__device__ __nv_bfloat16 g_Ebf[(size_t)NROWS * DDIM];    // 128 MB  bf16 embeddings
__device__ __nv_bfloat16 g_W1bf[(size_t)HDIM * DDIM];    // 1 MB    W1^T  [n][k]
__device__ __nv_bfloat16 g_Wa1bf[(size_t)HHALF * HDIM];  // 0.25 MB Wa1^T [n][k]
__device__ __nv_bfloat16 g_Hbf[(size_t)NROWS * HDIM];    // 64 MB   region_emb bf16
__device__ float g_scores[NROWS];
__device__ float g_w[NROWS];
__device__ float g_PF[RREG * NCHUNK * HDIM];

__device__ __forceinline__ float gelu_exact(float x) {
    return 0.5f * x * (1.0f + erff(x * 0.7071067811865476f));
}

__device__ __forceinline__ uint32_t smem_u32(const void* p) {
    uint32_t a;
    asm("{ .reg .u64 t; cvta.to.shared.u64 t, %1; cvt.u32.u64 %0, t; }" : "=r"(a) : "l"(p));
    return a;
}

// ---------------- baseline-ISA tensor-core primitives --------------------------
__device__ __forceinline__ void ldmatrix_x4(uint32_t* r, uint32_t addr) {
    asm volatile("ldmatrix.sync.aligned.m8n8.x4.shared.b16 {%0,%1,%2,%3}, [%4];"
                 : "=r"(r[0]), "=r"(r[1]), "=r"(r[2]), "=r"(r[3]) : "r"(addr));
}
__device__ __forceinline__ void mma_bf16(float* d, const uint32_t* a, const uint32_t* b) {
    asm volatile(
        "mma.sync.aligned.m16n8k16.row.col.f32.bf16.bf16.f32 "
        "{%0,%1,%2,%3}, {%4,%5,%6,%7}, {%8,%9}, {%0,%1,%2,%3};"
        : "+f"(d[0]), "+f"(d[1]), "+f"(d[2]), "+f"(d[3])
        : "r"(a[0]), "r"(a[1]), "r"(a[2]), "r"(a[3]), "r"(b[0]), "r"(b[1]));
}
__device__ __forceinline__ void cp_async16(uint32_t smem_addr, const void* gptr) {
    asm volatile("cp.async.cg.shared.global [%0], [%1], 16;"
                 :: "r"(smem_addr), "l"(gptr) : "memory");
}
#define CP_ASYNC_COMMIT() asm volatile("cp.async.commit_group;" ::: "memory")
#define CP_ASYNC_WAIT(n)  asm volatile("cp.async.wait_group %0;" :: "n"(n) : "memory")

// ---------------- conversion kernels ------------------------------------------
__global__ __launch_bounds__(256) void conv_bf16(const float* __restrict__ in,
                                                 __nv_bfloat16* __restrict__ out) {
    size_t i = ((size_t)blockIdx.x * 256 + threadIdx.x) * 8;
    float4 a = *reinterpret_cast<const float4*>(in + i);
    float4 b = *reinterpret_cast<const float4*>(in + i + 4);
    __nv_bfloat162 p0 = __float22bfloat162_rn(make_float2(a.x, a.y));
    __nv_bfloat162 p1 = __float22bfloat162_rn(make_float2(a.z, a.w));
    __nv_bfloat162 p2 = __float22bfloat162_rn(make_float2(b.x, b.y));
    __nv_bfloat162 p3 = __float22bfloat162_rn(make_float2(b.z, b.w));
    uint4 o;
    o.x = *reinterpret_cast<uint32_t*>(&p0);
    o.y = *reinterpret_cast<uint32_t*>(&p1);
    o.z = *reinterpret_cast<uint32_t*>(&p2);
    o.w = *reinterpret_cast<uint32_t*>(&p3);
    *reinterpret_cast<uint4*>(out + i) = o;
}

// out[n*K + k] = bf16(in[k*N + n])
__global__ __launch_bounds__(256) void transpose_bf16(const float* __restrict__ in,
                                                      __nv_bfloat16* __restrict__ out,
                                                      int K, int N) {
    int idx = blockIdx.x * 256 + threadIdx.x;
    int k = idx / N, n = idx % N;
    out[(size_t)n * K + k] = __float2bfloat16(in[idx]);
}

__global__ __launch_bounds__(1024) void zero_scores() {
    g_scores[blockIdx.x * 1024 + threadIdx.x] = 0.0f;
}

// ---------------- mma.sync GEMM: C = act(A[MxK] @ Bt[NxK]^T + bias) ------------
// CTA tile 128x128x32, 8 warps (2x4), warp tile 64x32.
// 3-stage cp.async pipeline, ONE __syncthreads per K-iter:
//   wait(t done) ; sync ; compute buf t%3 ; issue load t+2 into buf (t+2)%3
// Safe: load of buf (t+2)%3 is issued after iter-t's barrier, and all warps at
// that barrier have finished iter t-1's reads of buf (t-1)%3 == (t+2)%3.
// SMEM row = 32 bf16 (64B), 16B chunks swizzled by chunk ^= (row>>1)&3.
// SCORE: instead of storing C, accumulate sum_col tanh(..)*Wa2[col] into
// g_scores[row] via quad-shuffle reduction + atomicAdd (ba2 dropped: softmax
// is shift-invariant).
template <int ACT, bool WRITE_F32, bool WRITE_BF16, bool SCORE>
__global__ __launch_bounds__(256)
void gemm_mma(const __nv_bfloat16* __restrict__ A, const __nv_bfloat16* __restrict__ Bt,
              const float* __restrict__ bias, float* __restrict__ C,
              __nv_bfloat16* __restrict__ Cbf, const float* __restrict__ Wa2,
              int K, int N)
{
    __shared__ __nv_bfloat16 sA[3][128 * 32];
    __shared__ __nv_bfloat16 sB[3][128 * 32];

    const int tid  = threadIdx.x;
    const int lane = tid & 31;
    const int wid  = tid >> 5;
    const int wm   = wid >> 2;          // 0..1  -> rows wm*64
    const int wn   = wid & 3;           // 0..3  -> cols wn*32
    const int m0   = blockIdx.y * 128;
    const int n0   = blockIdx.x * 128;

    float acc[4][4][4];
#pragma unroll
    for (int i = 0; i < 4; i++)
#pragma unroll
        for (int j = 0; j < 4; j++)
#pragma unroll
            for (int v = 0; v < 4; v++) acc[i][j][v] = 0.0f;

    uint32_t sAb[3], sBb[3];
#pragma unroll
    for (int s = 0; s < 3; s++) { sAb[s] = smem_u32(sA[s]); sBb[s] = smem_u32(sB[s]); }

    // per-thread load coords: 512 chunks of 16B per tile, 2 per thread
    const int f0row = (tid + 0)   >> 2, f0ch = (tid + 0)   & 3;
    const int f1row = (tid + 256) >> 2, f1ch = (tid + 256) & 3;
    const uint32_t d0 = f0row * 64 + ((f0ch ^ ((f0row >> 1) & 3)) << 4);
    const uint32_t d1 = f1row * 64 + ((f1ch ^ ((f1row >> 1) & 3)) << 4);

    auto load_tile = [&](int stage, int k0) {
        cp_async16(sAb[stage] + d0, A  + (size_t)(m0 + f0row) * K + k0 + f0ch * 8);
        cp_async16(sAb[stage] + d1, A  + (size_t)(m0 + f1row) * K + k0 + f1ch * 8);
        cp_async16(sBb[stage] + d0, Bt + (size_t)(n0 + f0row) * K + k0 + f0ch * 8);
        cp_async16(sBb[stage] + d1, Bt + (size_t)(n0 + f1row) * K + k0 + f1ch * 8);
        CP_ASYNC_COMMIT();
    };

    const int ntiles = K >> 5;          // K/32  (>=16 for our shapes)
    load_tile(0, 0);
    load_tile(1, 32);

    for (int t = 0; t < ntiles; t++) {
        if (t + 1 < ntiles) { CP_ASYNC_WAIT(1); } else { CP_ASYNC_WAIT(0); }
        __syncthreads();

        const int s = t % 3;
        const uint32_t aBase = sAb[s];
        const uint32_t bBase = sBb[s];

#pragma unroll
        for (int ks = 0; ks < 2; ks++) {
            uint32_t aF[4][4];
#pragma unroll
            for (int mi = 0; mi < 4; mi++) {
                int row = wm * 64 + mi * 16 + (lane & 15);
                int ci  = ks * 2 + (lane >> 4);
                uint32_t addr = aBase + row * 64 + (((ci ^ ((row >> 1) & 3))) << 4);
                ldmatrix_x4(aF[mi], addr);
            }
            uint32_t bF[4][2];
#pragma unroll
            for (int p = 0; p < 2; p++) {
                int row = wn * 32 + p * 16 + ((lane & 7) | ((lane & 16) >> 1));
                int ci  = ks * 2 + ((lane >> 3) & 1);
                uint32_t addr = bBase + row * 64 + (((ci ^ ((row >> 1) & 3))) << 4);
                uint32_t r[4];
                ldmatrix_x4(r, addr);
                bF[2 * p + 0][0] = r[0]; bF[2 * p + 0][1] = r[1];
                bF[2 * p + 1][0] = r[2]; bF[2 * p + 1][1] = r[3];
            }
#pragma unroll
            for (int mi = 0; mi < 4; mi++)
#pragma unroll
                for (int j = 0; j < 4; j++)
                    mma_bf16(acc[mi][j], aF[mi], bF[j]);
        }

        if (t + 2 < ntiles) load_tile((t + 2) % 3, (t + 2) << 5);
    }

    // epilogue: bias + activation + store / score-reduce
    const int g  = lane >> 2;           // row group 0..7
    const int cc = (lane & 3) * 2;      // col pair
    float rowpart[4][2];
    if (SCORE) {
#pragma unroll
        for (int mi = 0; mi < 4; mi++) { rowpart[mi][0] = 0.0f; rowpart[mi][1] = 0.0f; }
    }
#pragma unroll
    for (int mi = 0; mi < 4; mi++) {
#pragma unroll
        for (int j = 0; j < 4; j++) {
            int col = n0 + wn * 32 + j * 8 + cc;
            float b0 = bias[col], b1 = bias[col + 1];
            float w0 = 0.0f, w1 = 0.0f;
            if (SCORE) { w0 = Wa2[col]; w1 = Wa2[col + 1]; }
#pragma unroll
            for (int h = 0; h < 2; h++) {   // h=0: row g, h=1: row g+8
                int row = m0 + wm * 64 + mi * 16 + g + h * 8;
                float v0 = acc[mi][j][2 * h + 0] + b0;
                float v1 = acc[mi][j][2 * h + 1] + b1;
                if (ACT == 1) { v0 = gelu_exact(v0); v1 = gelu_exact(v1); }
                if (ACT == 2) { v0 = tanhf(v0); v1 = tanhf(v1); }
                if (SCORE) {
                    rowpart[mi][h] = fmaf(v0, w0, rowpart[mi][h]);
                    rowpart[mi][h] = fmaf(v1, w1, rowpart[mi][h]);
                }
                if (WRITE_F32) {
                    float2 o; o.x = v0; o.y = v1;
                    *reinterpret_cast<float2*>(C + (size_t)row * N + col) = o;
                }
                if (WRITE_BF16) {
                    __nv_bfloat162 q = __float22bfloat162_rn(make_float2(v0, v1));
                    *reinterpret_cast<uint32_t*>(Cbf + (size_t)row * N + col) =
                        *reinterpret_cast<uint32_t*>(&q);
                }
            }
        }
    }
    if (SCORE) {
        // quad reduction: lanes g*4..g*4+3 hold the same rows; sum across lane&3
#pragma unroll
        for (int mi = 0; mi < 4; mi++) {
#pragma unroll
            for (int h = 0; h < 2; h++) {
                float v = rowpart[mi][h];
                v += __shfl_xor_sync(0xffffffffu, v, 1);
                v += __shfl_xor_sync(0xffffffffu, v, 2);
                if ((lane & 3) == 0) {
                    int row = m0 + wm * 64 + mi * 16 + g + h * 8;
                    atomicAdd(g_scores + row, v);
                }
            }
        }
    }
}

// ---------------- per-region softmax -------------------------------------------
__global__ __launch_bounds__(256)
void softmax_region()
{
    int r = blockIdx.x;
    int tid = threadIdx.x;
    __shared__ float red[256];

    float mx = -1e30f;
    for (int m = tid; m < MPATCH; m += 256) mx = fmaxf(mx, g_scores[m * RREG + r]);
    red[tid] = mx; __syncthreads();
    for (int o = 128; o > 0; o >>= 1) { if (tid < o) red[tid] = fmaxf(red[tid], red[tid + o]); __syncthreads(); }
    mx = red[0]; __syncthreads();

    float sm = 0.0f;
    for (int m = tid; m < MPATCH; m += 256) sm += expf(g_scores[m * RREG + r] - mx);
    red[tid] = sm; __syncthreads();
    for (int o = 128; o > 0; o >>= 1) { if (tid < o) red[tid] += red[tid + o]; __syncthreads(); }
    float inv = 1.0f / red[0];

    for (int m = tid; m < MPATCH; m += 256)
        g_w[m * RREG + r] = expf(g_scores[m * RREG + r] - mx) * inv;
}

// ---------------- weighted pooling (bf16 source, fp32 accumulate) --------------
__global__ __launch_bounds__(256)
void pool_partial()
{
    int r  = blockIdx.x;    // 16 regions
    int ch = blockIdx.y;    // 32 chunks
    int c2 = threadIdx.x;   // 256 threads, 2 cols each
    float acc0 = 0.0f, acc1 = 0.0f;
    int m0 = ch * MCHUNK;
#pragma unroll 4
    for (int mm = 0; mm < MCHUNK; mm++) {
        int row = (m0 + mm) * RREG + r;
        float w = g_w[row];
        __nv_bfloat162 hv = *reinterpret_cast<const __nv_bfloat162*>(
            g_Hbf + (size_t)row * HDIM + c2 * 2);
        float2 hf = __bfloat1622float2(hv);
        acc0 = fmaf(hf.x, w, acc0);
        acc1 = fmaf(hf.y, w, acc1);
    }
    g_PF[(r * NCHUNK + ch) * HDIM + c2 * 2 + 0] = acc0;
    g_PF[(r * NCHUNK + ch) * HDIM + c2 * 2 + 1] = acc1;
}

// ---------------- single-block slide pipeline ----------------------------------
__global__ __launch_bounds__(512)
void slide_kernel(const float* __restrict__ Ws,  const float* __restrict__ bs,
                  const float* __restrict__ Wsa1, const float* __restrict__ bsa1,
                  const float* __restrict__ Wsa2, const float* __restrict__ bsa2,
                  const float* __restrict__ Wc1, const float* __restrict__ bc1,
                  const float* __restrict__ Wc2, const float* __restrict__ bc2,
                  float* __restrict__ out)
{
    extern __shared__ float smf[];
    float* sRF   = smf;
    float* sSE   = smf + 8192;
    float* sRep  = smf + 16384;
    float* sAtt  = smf + 16896;
    float* sWred = smf + 16912;

    int tid  = threadIdx.x;
    int lane = tid & 31, wp = tid >> 5;

    for (int idx = tid; idx < RREG * HDIM; idx += 512) {
        int r = idx >> 9, c = idx & 511;
        float s = 0.0f;
#pragma unroll
        for (int j = 0; j < NCHUNK; j++) s += g_PF[(r * NCHUNK + j) * HDIM + c];
        sRF[idx] = s;
    }
    __syncthreads();

    {
        float accv[RREG];
        float bg = bs[tid];
#pragma unroll
        for (int r = 0; r < RREG; r++) accv[r] = bg;
        for (int h = 0; h < HDIM; h++) {
            float wg = Ws[h * HDIM + tid];
#pragma unroll
            for (int r = 0; r < RREG; r++) accv[r] = fmaf(sRF[r * HDIM + h], wg, accv[r]);
        }
#pragma unroll
        for (int r = 0; r < RREG; r++) sSE[r * HDIM + tid] = gelu_exact(accv[r]);
    }
    __syncthreads();

    {
        float contrib[RREG];
        if (tid < HHALF) {
            float acc[RREG];
            float bk = bsa1[tid];
#pragma unroll
            for (int r = 0; r < RREG; r++) acc[r] = bk;
            for (int h = 0; h < HDIM; h++) {
                float wv = Wsa1[h * HHALF + tid];
#pragma unroll
                for (int r = 0; r < RREG; r++) acc[r] = fmaf(sSE[r * HDIM + h], wv, acc[r]);
            }
            float w2 = Wsa2[tid];
#pragma unroll
            for (int r = 0; r < RREG; r++) contrib[r] = tanhf(acc[r]) * w2;
        } else {
#pragma unroll
            for (int r = 0; r < RREG; r++) contrib[r] = 0.0f;
        }
#pragma unroll
        for (int r = 0; r < RREG; r++) {
            float v = contrib[r];
#pragma unroll
            for (int o = 16; o > 0; o >>= 1) v += __shfl_down_sync(0xffffffffu, v, o);
            if (lane == 0) sWred[wp * RREG + r] = v;
        }
        __syncthreads();
        if (tid < RREG) {
            float s = 0.0f;
#pragma unroll
            for (int j = 0; j < 16; j++) s += sWred[j * RREG + tid];
            sAtt[tid] = s + bsa2[0];
        }
        __syncthreads();
        if (tid == 0) {
            float mx = -1e30f;
            for (int r = 0; r < RREG; r++) mx = fmaxf(mx, sAtt[r]);
            float sum = 0.0f;
            for (int r = 0; r < RREG; r++) { float e = expf(sAtt[r] - mx); sAtt[r] = e; sum += e; }
            float inv = 1.0f / sum;
            for (int r = 0; r < RREG; r++) sAtt[r] *= inv;
        }
        __syncthreads();
    }

    {
        float rep = 0.0f;
#pragma unroll
        for (int r = 0; r < RREG; r++) rep = fmaf(sSE[r * HDIM + tid], sAtt[r], rep);
        sRep[tid] = rep;
    }
    __syncthreads();

    {
        float c0 = 0.0f, c1 = 0.0f;
        if (tid < HHALF) {
            float a = bc1[tid];
            for (int h = 0; h < HDIM; h++) a = fmaf(sRep[h], Wc1[h * HHALF + tid], a);
            float g = gelu_exact(a);
            c0 = g * Wc2[tid * 2 + 0];
            c1 = g * Wc2[tid * 2 + 1];
        }
#pragma unroll
        for (int o = 16; o > 0; o >>= 1) {
            c0 += __shfl_down_sync(0xffffffffu, c0, o);
            c1 += __shfl_down_sync(0xffffffffu, c1, o);
        }
        if (lane == 0) { sWred[wp * 2] = c0; sWred[wp * 2 + 1] = c1; }
        __syncthreads();
        if (tid == 0) {
            float l0 = 0.0f, l1 = 0.0f;
#pragma unroll
            for (int j = 0; j < 16; j++) { l0 += sWred[j * 2]; l1 += sWred[j * 2 + 1]; }
            out[0] = l0 + bc2[0];
            out[1] = l1 + bc2[1];
        }
    }
}

// -------------------------------- launch ----------------------------------------
extern "C" void kernel_launch(void* const* d_in, const int* in_sizes, int n_in,
                              void* d_out, int out_size)
{
    const float* emb  = (const float*)d_in[0];
    const float* W1   = (const float*)d_in[1];
    const float* b1   = (const float*)d_in[2];
    const float* Wa1  = (const float*)d_in[3];
    const float* ba1  = (const float*)d_in[4];
    const float* Wa2  = (const float*)d_in[5];
    const float* Ws   = (const float*)d_in[7];
    const float* bs   = (const float*)d_in[8];
    const float* Wsa1 = (const float*)d_in[9];
    const float* bsa1 = (const float*)d_in[10];
    const float* Wsa2 = (const float*)d_in[11];
    const float* bsa2 = (const float*)d_in[12];
    const float* Wc1  = (const float*)d_in[13];
    const float* bc1  = (const float*)d_in[14];
    const float* Wc2  = (const float*)d_in[15];
    const float* bc2  = (const float*)d_in[16];
    float* out = (float*)d_out;

    __nv_bfloat16 *gEbf, *gW1bf, *gWa1bf, *gHbf;
    cudaGetSymbolAddress((void**)&gEbf, g_Ebf);
    cudaGetSymbolAddress((void**)&gW1bf, g_W1bf);
    cudaGetSymbolAddress((void**)&gWa1bf, g_Wa1bf);
    cudaGetSymbolAddress((void**)&gHbf, g_Hbf);

    // 0. bf16 conversions
    conv_bf16<<<(size_t)NROWS * DDIM / (256 * 8), 256>>>(emb, gEbf);
    transpose_bf16<<<(DDIM * HDIM) / 256, 256>>>(W1, gW1bf, DDIM, HDIM);
    transpose_bf16<<<(HDIM * HHALF) / 256, 256>>>(Wa1, gWa1bf, HDIM, HHALF);

    // 1. region encoder: Hbf = bf16(gelu(E @ W1 + b1))   (65536 x 1024 x 512)
    gemm_mma<1, false, true, false><<<dim3(HDIM / 128, NROWS / 128), 256>>>(
        gEbf, gW1bf, b1, (float*)nullptr, gHbf, (const float*)nullptr, DDIM, HDIM);

    // 2. fused attention-score GEMM: scores[i] = sum_k tanh(Hbf@Wa1+ba1)[i,k]*Wa2[k]
    //    (ba2 dropped — softmax is shift-invariant)
    zero_scores<<<NROWS / 1024, 1024>>>();
    gemm_mma<2, false, false, true><<<dim3(HHALF / 128, NROWS / 128), 256>>>(
        gHbf, gWa1bf, ba1, (float*)nullptr, (__nv_bfloat16*)nullptr, Wa2, HDIM, HHALF);

    // 3. per-region softmax
    softmax_region<<<RREG, 256>>>();
    // 4. weighted pool partials (from bf16 H)
    pool_partial<<<dim3(RREG, NCHUNK), 256>>>();
    // 5. slide encoder + attention + classifier
    const int SLIDE_SMEM = (2 * RREG * HDIM + HDIM + RREG + 256) * (int)sizeof(float);
    cudaFuncSetAttribute(slide_kernel, cudaFuncAttributeMaxDynamicSharedMemorySize, SLIDE_SMEM);
    slide_kernel<<<1, 512, SLIDE_SMEM>>>(Ws, bs, Wsa1, bsa1, Wsa2, bsa2,
                                         Wc1, bc1, Wc2, bc2, out);
}